// round 16
// baseline (speedup 1.0000x reference)
#include <cuda_runtime.h>
#include <cuda_bf16.h>
#include <math.h>
#include <stdint.h>

#define DEV_INLINE __device__ __forceinline__

constexpr int Bn = 32, Ln = 256, DNn = 512;
constexpr int ROWS = Bn * Ln;            // 8192 (b,l) rows
constexpr int EROWS = ROWS * Ln;         // 2,097,152 edge rows
constexpr int FNn = 1024;
constexpr float EPSc = 1e-5f;

// ---------------- device scratch ----------------
__device__ float g_hln[ROWS * DNn];
__device__ float g_qkv[ROWS * 3 * DNn];       // only Q region (cols 0..511) written
__device__ float g_vatt[ROWS * DNn];
__device__ float g_h2[ROWS * DNn];
__device__ float g_hff[ROWS * DNn];
__device__ float g_t[ROWS * FNn];
__device__ uint32_t g_Hb[(size_t)EROWS * 16];     // H_hat + mask, bf16x2
__device__ uint32_t g_gateb[(size_t)EROWS * 16];  // sigmoid(G+mask), bf16x2
__device__ __nv_bfloat16 g_Ab[(size_t)EROWS * 32];// A_hat (scaled), bf16
__device__ uint32_t g_Wt[(size_t)ROWS * 4096];    // softmax weights, bf16 m-pairs
// bf16 fragment-packed edge weights (see packB); bf16 K and V
__device__ __nv_bfloat16 g_WEGb[64 * 64];
__device__ __nv_bfloat16 g_WOeb[32 * 64];
__device__ __nv_bfloat16 g_We1b[64 * 128];
__device__ __nv_bfloat16 g_We2b[128 * 64];
__device__ __nv_bfloat162 g_kb[(size_t)ROWS * 256];   // [(row)*256 + dp*32 + h]
__device__ __nv_bfloat162 g_vb[(size_t)ROWS * 256];   // [(row)*256 + kp*32 + h]

DEV_INLINE uint32_t packbf(float a, float b) {
    __nv_bfloat162 h2 = __floats2bfloat162_rn(a, b);
    return *(uint32_t*)&h2;
}

DEV_INLINE float to_tf32(float x) {
    float y;
    asm("cvt.rna.tf32.f32 %0, %1;" : "=f"(y) : "f"(x));
    return y;
}

DEV_INLINE void mma8(float c[4], uint32_t a0, uint32_t a1, uint32_t a2, uint32_t a3,
                     uint32_t b0, uint32_t b1)
{
    asm volatile(
        "mma.sync.aligned.m16n8k8.row.col.f32.tf32.tf32.f32 "
        "{%0,%1,%2,%3},{%4,%5,%6,%7},{%8,%9},{%0,%1,%2,%3};"
        : "+f"(c[0]), "+f"(c[1]), "+f"(c[2]), "+f"(c[3])
        : "r"(a0), "r"(a1), "r"(a2), "r"(a3), "r"(b0), "r"(b1));
}

DEV_INLINE void mma16(float c[4], uint32_t a0, uint32_t a1, uint32_t a2, uint32_t a3,
                      uint32_t b0, uint32_t b1)
{
    asm volatile(
        "mma.sync.aligned.m16n8k16.row.col.f32.bf16.bf16.f32 "
        "{%0,%1,%2,%3},{%4,%5,%6,%7},{%8,%9},{%0,%1,%2,%3};"
        : "+f"(c[0]), "+f"(c[1]), "+f"(c[2]), "+f"(c[3])
        : "r"(a0), "r"(a1), "r"(a2), "r"(a3), "r"(b0), "r"(b1));
}

// bf16 warp GEMM, m16n8k16. A in smem as u32 (bf16x2), sb2 = u32 words per row.
template<int TM, int NTW, int S, int N>
DEV_INLINE void wgemm_b(float c[TM][NTW][4], const uint32_t* __restrict__ As, int sb2,
                        const uint32_t* __restrict__ Bp, int g, int qt)
{
    #pragma unroll
    for (int t = 0; t < (S + 1) / 2; t++) {
        uint4 bq[NTW];
        #pragma unroll
        for (int j = 0; j < NTW; j++)
            bq[j] = *(const uint4*)&Bp[(t * (N * 4) + (j * 8 + g) * 4 + qt) * 4];
        #pragma unroll
        for (int se = 0; se < 2; se++) {
            int s = 2 * t + se;
            if (s >= S) break;
            #pragma unroll
            for (int tm = 0; tm < TM; tm++) {
                const uint32_t* Ar = As + tm * 16 * sb2;
                uint32_t a0 = Ar[(g)     * sb2 + 8 * s + qt];
                uint32_t a2 = Ar[(g)     * sb2 + 8 * s + qt + 4];
                uint32_t a1 = Ar[(g + 8) * sb2 + 8 * s + qt];
                uint32_t a3 = Ar[(g + 8) * sb2 + 8 * s + qt + 4];
                #pragma unroll
                for (int j = 0; j < NTW; j++) {
                    uint32_t b0 = se ? bq[j].z : bq[j].x;
                    uint32_t b1 = se ? bq[j].w : bq[j].y;
                    mma16(c[tm][j], a0, a1, a2, a3, b0, b1);
                }
            }
        }
    }
}

// bf16 fragment pack index: element (k,n) of a KxN col-fragment weight.
DEV_INLINE int packB(int n, int k, int N) {
    int p = k >> 1, lo = k & 1;
    int qt = p & 3, half = (p >> 2) & 1, s = p >> 3;
    int t = s >> 1, se = s & 1;
    int u32i = (t * (N * 4) + n * 4 + qt) * 4 + se * 2 + half;
    return u32i * 2 + lo;
}

__global__ void pack_weights(const float* __restrict__ W_E, const float* __restrict__ W_G,
                             const float* __restrict__ W_Oe, const float* __restrict__ W_e1,
                             const float* __restrict__ W_e2)
{
    int i = blockIdx.x * 256 + threadIdx.x;
    if (i < 4096) {                       // WEG: K=64, N=64
        int k = i >> 6, n = i & 63;
        float v = n < 32 ? W_E[k * 32 + n] : W_G[k * 32 + n - 32];
        g_WEGb[packB(n, k, 64)] = __float2bfloat16(v);
    } else if (i < 6144) {                // WOe: K=32, N=64
        int j = i - 4096; int k = j >> 6, n = j & 63;
        g_WOeb[packB(n, k, 64)] = __float2bfloat16(W_Oe[j]);
    } else if (i < 14336) {               // We1: K=64, N=128
        int j = i - 6144; int k = j >> 7, n = j & 127;
        g_We1b[packB(n, k, 128)] = __float2bfloat16(W_e1[j]);
    } else if (i < 22528) {               // We2: K=128, N=64
        int j = i - 14336; int k = j >> 6, n = j & 63;
        g_We2b[packB(n, k, 64)] = __float2bfloat16(W_e2[j]);
    }
}

// ---------------- QK precompute: A_hat, 4 l's per thread --------------------
constexpr int QK_SMEM_BYTES = 64 * 256 * 4;   // 65536

__global__ void __launch_bounds__(256, 2) qk_kernel()
{
    extern __shared__ uint32_t ks[];   // [64][256] bf16x2 words
    int blk = blockIdx.x;
    int lt = blk & 7, mt = (blk >> 3) & 3, b = blk >> 5;
    int m0 = mt * 64, l0 = lt * 32;
    int tid = threadIdx.x;

    const uint4* Ksrc = (const uint4*)(g_kb + ((size_t)(b * 256) + m0) * 256);
    uint4* Kdst = (uint4*)ks;
    #pragma unroll
    for (int i = 0; i < 16; i++)
        Kdst[tid + i * 256] = Ksrc[tid + i * 256];
    __syncthreads();

    int h = tid & 31, lg = tid >> 5;
    int l = l0 + lg * 4;
    int bl = b * 256 + l;

    float q[4][16];
    #pragma unroll
    for (int li = 0; li < 4; li++) {
        const float* Qp = g_qkv + (size_t)(bl + li) * 1536 + h;
        #pragma unroll
        for (int d = 0; d < 16; d++) q[li][d] = Qp[d * 32];
    }

    __nv_bfloat16* Ad0 = g_Ab + ((size_t)(bl + 0) * 256 + m0) * 32 + h;
    __nv_bfloat16* Ad1 = g_Ab + ((size_t)(bl + 1) * 256 + m0) * 32 + h;
    __nv_bfloat16* Ad2 = g_Ab + ((size_t)(bl + 2) * 256 + m0) * 32 + h;
    __nv_bfloat16* Ad3 = g_Ab + ((size_t)(bl + 3) * 256 + m0) * 32 + h;

    #pragma unroll 2
    for (int m = 0; m < 64; m++) {
        const uint32_t* Kp = ks + m * 256 + h;
        float kf[16];
        #pragma unroll
        for (int dp = 0; dp < 8; dp++) {
            uint32_t wv = Kp[dp * 32];
            kf[2 * dp]     = __uint_as_float(wv << 16);
            kf[2 * dp + 1] = __uint_as_float(wv & 0xffff0000u);
        }
        float a0 = 0.f, a1 = 0.f, a2 = 0.f, a3 = 0.f;
        #pragma unroll
        for (int d = 0; d < 16; d++) {
            a0 += q[0][d] * kf[d];
            a1 += q[1][d] * kf[d];
            a2 += q[2][d] * kf[d];
            a3 += q[3][d] * kf[d];
        }
        Ad0[(size_t)m * 32] = __float2bfloat16(a0 * 0.25f);
        Ad1[(size_t)m * 32] = __float2bfloat16(a1 * 0.25f);
        Ad2[(size_t)m * 32] = __float2bfloat16(a2 * 0.25f);
        Ad3[(size_t)m * 32] = __float2bfloat16(a3 * 0.25f);
    }
}

// ---------------- LayerNorm over 512, one block per row ----------------
__global__ void __launch_bounds__(128) ln512_kernel(
    const float* __restrict__ x, const float* __restrict__ g,
    const float* __restrict__ b, float* __restrict__ y)
{
    int row = blockIdx.x, tid = threadIdx.x;
    const float4* xr = (const float4*)(x + (size_t)row * 512);
    float4 v = xr[tid];
    float s  = v.x + v.y + v.z + v.w;
    float s2 = v.x*v.x + v.y*v.y + v.z*v.z + v.w*v.w;
    #pragma unroll
    for (int o = 16; o; o >>= 1) {
        s  += __shfl_xor_sync(0xffffffffu, s,  o);
        s2 += __shfl_xor_sync(0xffffffffu, s2, o);
    }
    __shared__ float aS[4], aS2[4];
    if ((tid & 31) == 0) { aS[tid >> 5] = s; aS2[tid >> 5] = s2; }
    __syncthreads();
    s  = aS[0] + aS[1] + aS[2] + aS[3];
    s2 = aS2[0] + aS2[1] + aS2[2] + aS2[3];
    float mean = s * (1.f / 512.f);
    float rstd = rsqrtf(s2 * (1.f / 512.f) - mean * mean + EPSc);
    int c = tid * 4;
    float4 gv = *(const float4*)(g + c);
    float4 bv = *(const float4*)(b + c);
    float4 o;
    o.x = (v.x - mean) * rstd * gv.x + bv.x;
    o.y = (v.y - mean) * rstd * gv.y + bv.y;
    o.z = (v.z - mean) * rstd * gv.z + bv.z;
    o.w = (v.w - mean) * rstd * gv.w + bv.w;
    ((float4*)(y + (size_t)row * 512))[tid] = o;
}

// ------- tf32 tensor GEMM, 64-bit paired smem operands (h-path) ---------------
// A pairs: As2[r][ks*4+qt] = (A[r][ks*8+qt], A[r][ks*8+qt+4])       (stride 34)
// B pairs: Bs2[ks*4+qt][n] = (B[ks*8+qt][n], B[ks*8+qt+4][n])      (stride 66)
// MODE 1: +bias+res ; MODE 2: elu(+bias) ; MODE 3: QKV with K/V bf16 pack
constexpr int TG_SMEM_BYTES = (128 * 34 + 32 * 66) * 8;   // 51712
template<int MODE>
__global__ void __launch_bounds__(256) tgemm_tf(
    const float* __restrict__ A, const float* __restrict__ B, float* __restrict__ C,
    const float* __restrict__ bias, const float* __restrict__ res,
    int M, int N, int K)
{
    extern __shared__ float ts[];
    float2* As2 = (float2*)ts;                  // 128 x 34 float2
    float2* Bs2 = (float2*)(ts + 128 * 34 * 2); // 32 x 66 float2
    int tid = threadIdx.x;
    int row0 = blockIdx.y * 128, col0 = blockIdx.x * 64;
    int w = tid >> 5;
    int g = (tid & 31) >> 2, qt = tid & 3;
    float acc[8][4] = {};

    for (int k0 = 0; k0 < K; k0 += 64) {
        // stage A: 128 rows x 8 octets, pairs (c, c+4)
        #pragma unroll
        for (int it = 0; it < 4; it++) {
            int idx = tid + it * 256;
            int r = idx >> 3, oct = idx & 7;
            const float* ap = &A[(size_t)(row0 + r) * K + k0 + oct * 8];
            float4 v0 = *(const float4*)ap;
            float4 v1 = *(const float4*)(ap + 4);
            float2* dst = As2 + r * 34 + oct * 4;
            dst[0] = make_float2(to_tf32(v0.x), to_tf32(v1.x));
            dst[1] = make_float2(to_tf32(v0.y), to_tf32(v1.y));
            dst[2] = make_float2(to_tf32(v0.z), to_tf32(v1.z));
            dst[3] = make_float2(to_tf32(v0.w), to_tf32(v1.w));
        }
        // stage B: 32 pair-rows x 16 col-quads, pairs (k+qt, k+qt+4)
        #pragma unroll
        for (int it = 0; it < 2; it++) {
            int idx = tid + it * 256;
            int p = idx >> 4, quad = idx & 15;
            int ksr = p >> 2, qtr = p & 3;
            const float* bp = &B[(size_t)(k0 + ksr * 8 + qtr) * N + col0 + quad * 4];
            float4 v0 = *(const float4*)bp;
            float4 v1 = *(const float4*)(bp + 4 * N);
            float2* dst = Bs2 + p * 66 + quad * 4;
            dst[0] = make_float2(to_tf32(v0.x), to_tf32(v1.x));
            dst[1] = make_float2(to_tf32(v0.y), to_tf32(v1.y));
            dst[2] = make_float2(to_tf32(v0.z), to_tf32(v1.z));
            dst[3] = make_float2(to_tf32(v0.w), to_tf32(v1.w));
        }
        __syncthreads();
        const float2* Ar = As2 + (w * 16) * 34;
        #pragma unroll
        for (int ks = 0; ks < 8; ks++) {
            float2 Aw0 = Ar[(g)     * 34 + ks * 4 + qt];
            float2 Aw1 = Ar[(g + 8) * 34 + ks * 4 + qt];
            uint32_t a0 = __float_as_uint(Aw0.x), a2 = __float_as_uint(Aw0.y);
            uint32_t a1 = __float_as_uint(Aw1.x), a3 = __float_as_uint(Aw1.y);
            const float2* Br = Bs2 + (ks * 4 + qt) * 66 + g;
            #pragma unroll
            for (int j = 0; j < 8; j++) {
                float2 Bw = Br[j * 8];
                mma8(acc[j], a0, a1, a2, a3,
                     __float_as_uint(Bw.x), __float_as_uint(Bw.y));
            }
        }
        __syncthreads();
    }
    if (MODE == 3 && col0 >= 512) {
        bool isK = (col0 < 1024);
        uint32_t* dstBase = (uint32_t*)(isK ? g_kb : g_vb);
        int obase = col0 - (isK ? 512 : 1024);
        #pragma unroll
        for (int j = 0; j < 4; j++) {
            int c = col0 + j * 8 + 2 * qt;
            int o = obase + j * 8 + 2 * qt;
            int dp = o >> 6, hh = o & 31;
            float b00 = bias[c],      b01 = bias[c + 1];
            float b10 = bias[c + 32], b11 = bias[c + 33];
            #pragma unroll
            for (int hf = 0; hf < 2; hf++) {
                int r = row0 + w * 16 + g + hf * 8;
                uint32_t* d = dstBase + (size_t)r * 256 + dp * 32 + hh;
                d[0] = packbf(acc[j][hf * 2 + 0] + b00, acc[j + 4][hf * 2 + 0] + b10);
                d[1] = packbf(acc[j][hf * 2 + 1] + b01, acc[j + 4][hf * 2 + 1] + b11);
            }
        }
        return;
    }
    #pragma unroll
    for (int j = 0; j < 8; j++) {
        int col = col0 + j * 8 + 2 * qt;
        #pragma unroll
        for (int hf = 0; hf < 2; hf++) {
            int r = row0 + w * 16 + g + hf * 8;
            float v0 = acc[j][hf * 2 + 0] + bias[col];
            float v1 = acc[j][hf * 2 + 1] + bias[col + 1];
            if (MODE == 1) {
                float2 rv = *(const float2*)&res[(size_t)r * N + col];
                v0 += rv.x; v1 += rv.y;
            }
            if (MODE == 2) {
                v0 = v0 > 0.f ? v0 : __expf(v0) - 1.f;
                v1 = v1 > 0.f ? v1 : __expf(v1) - 1.f;
            }
            float2 ov; ov.x = v0; ov.y = v1;
            *(float2*)&C[(size_t)r * N + col] = ov;
        }
    }
}

// LN of 64 rows x 64 cols: fp32 src (stride sstr) -> bf16x2 dst (dsb2 u32/row).
DEV_INLINE void ln64b(const float* __restrict__ src, int sstr, uint32_t* __restrict__ dst,
                      int dsb2, const float* __restrict__ gam,
                      const float* __restrict__ bet, int tid)
{
    int r = tid >> 2, sub = tid & 3;
    const float* p = src + r * sstr + sub * 16;
    float x[16]; float s = 0.f, s2 = 0.f;
    #pragma unroll
    for (int i = 0; i < 16; i += 4) {
        float4 v = *(const float4*)(p + i);
        x[i] = v.x; x[i+1] = v.y; x[i+2] = v.z; x[i+3] = v.w;
    }
    #pragma unroll
    for (int i = 0; i < 16; i++) { s += x[i]; s2 += x[i] * x[i]; }
    s  += __shfl_xor_sync(0xffffffffu, s, 1);  s  += __shfl_xor_sync(0xffffffffu, s, 2);
    s2 += __shfl_xor_sync(0xffffffffu, s2, 1); s2 += __shfl_xor_sync(0xffffffffu, s2, 2);
    float mean = s * (1.f / 64.f);
    float rstd = rsqrtf(s2 * (1.f / 64.f) - mean * mean + EPSc);
    uint32_t* d = dst + r * dsb2 + sub * 8;
    #pragma unroll
    for (int i = 0; i < 16; i += 2) {
        int c = sub * 16 + i;
        float y0 = (x[i]     - mean) * rstd * gam[c]     + bet[c];
        float y1 = (x[i + 1] - mean) * rstd * gam[c + 1] + bet[c + 1];
        d[i >> 1] = packbf(y0, y1);
    }
}

// Fused: load e tile from global, keep fp32 copy in sX, LN -> bf16x2 sXb.
DEV_INLINE void ln64g(const float* __restrict__ eg, float* __restrict__ sX,
                      uint32_t* __restrict__ sXb,
                      const float* __restrict__ gam, const float* __restrict__ bet, int tid)
{
    int r = tid >> 2, sub = tid & 3;
    const float* p = eg + r * 64 + sub * 16;
    float* q = sX + r * 68 + sub * 16;
    float x[16]; float s = 0.f, s2 = 0.f;
    #pragma unroll
    for (int i = 0; i < 16; i += 4) {
        float4 v = *(const float4*)(p + i);
        *(float4*)(q + i) = v;
        x[i] = v.x; x[i+1] = v.y; x[i+2] = v.z; x[i+3] = v.w;
    }
    #pragma unroll
    for (int i = 0; i < 16; i++) { s += x[i]; s2 += x[i] * x[i]; }
    s  += __shfl_xor_sync(0xffffffffu, s, 1);  s  += __shfl_xor_sync(0xffffffffu, s, 2);
    s2 += __shfl_xor_sync(0xffffffffu, s2, 1); s2 += __shfl_xor_sync(0xffffffffu, s2, 2);
    float mean = s * (1.f / 64.f);
    float rstd = rsqrtf(s2 * (1.f / 64.f) - mean * mean + EPSc);
    uint32_t* d = sXb + r * 36 + sub * 8;
    #pragma unroll
    for (int i = 0; i < 16; i += 2) {
        int c = sub * 16 + i;
        float y0 = (x[i]     - mean) * rstd * gam[c]     + bet[c];
        float y1 = (x[i + 1] - mean) * rstd * gam[c + 1] + bet[c + 1];
        d[i >> 1] = packbf(y0, y1);
    }
}

// ---------------- edge pipeline: 64 rows/CTA, 256 threads, 4 CTA/SM ------------
constexpr int EA_SMEM_BYTES = (4352 + 2304 + 1280 + 4352) * 4;  // 49152

__global__ void __launch_bounds__(256, 4) ea_kernel(
    const float* __restrict__ e, const float* __restrict__ mask,
    const float* __restrict__ lng, const float* __restrict__ lnb,
    const float* __restrict__ flg, const float* __restrict__ flb,
    const float* __restrict__ b_E,  const float* __restrict__ b_G,
    const float* __restrict__ b_Oe, const float* __restrict__ b_e1,
    const float* __restrict__ b_e2,
    float* __restrict__ e_out)
{
    extern __shared__ float sm[];
    float*    sX  = sm;                          // 64 x 68 fp32 (e, then e2)
    uint32_t* sXb = (uint32_t*)(sm + 4352);      // 64 x 36 u32 (eln/eff bf16x2)
    uint32_t* sAb = (uint32_t*)(sm + 6656);      // 64 x 20 u32 (H bf16x2)
    uint32_t* sTb = (uint32_t*)(sm + 7936);      // 64 x 68 u32 (T bf16x2)

    int tid = threadIdx.x;
    int blk = blockIdx.x;
    int bl  = blk >> 2, quad = blk & 3;
    int m0  = quad * 64;
    size_t R0 = (size_t)bl * 256 + m0;

    int w   = tid >> 5;
    int wm2 = w >> 2, wn = w & 3;
    int g   = (tid & 31) >> 2, qt = tid & 3;
    int rowb = wm2 * 32;

    const uint32_t* WEGu = (const uint32_t*)g_WEGb;
    const uint32_t* WOeu = (const uint32_t*)g_WOeb;
    const uint32_t* We1u = (const uint32_t*)g_We1b;
    const uint32_t* We2u = (const uint32_t*)g_We2b;

    ln64g(e + R0 * 64, sX, sXb, lng, lnb, tid);
    __syncthreads();

    float c1[2][2][4] = {};
    wgemm_b<2, 2, 4, 64>(c1, sXb + rowb * 36, 36, WEGu + wn * 256, g, qt);
    __syncthreads();

    {
        #pragma unroll
        for (int tm = 0; tm < 2; tm++) {
            float mk0 = mask[(size_t)bl * 256 + m0 + rowb + tm * 16 + g];
            float mk1 = mask[(size_t)bl * 256 + m0 + rowb + tm * 16 + g + 8];
            #pragma unroll
            for (int j = 0; j < 2; j++) {
                int colg = wn * 16 + j * 8 + 2 * qt;
                if (wn < 2) {
                    int col = colg;
                    float bv0 = b_E[col], bv1 = b_E[col + 1];
                    #pragma unroll
                    for (int hf = 0; hf < 2; hf++) {
                        int r = rowb + tm * 16 + g + hf * 8;
                        uint32_t aw = ((const uint32_t*)g_Ab)[(R0 + r) * 16 + (col >> 1)];
                        float2 Af = __bfloat1622float2(*(__nv_bfloat162*)&aw);
                        float H0 = fminf(fmaxf(Af.x, -5.f), 5.f) + c1[tm][j][hf * 2 + 0] + bv0;
                        float H1 = fminf(fmaxf(Af.y, -5.f), 5.f) + c1[tm][j][hf * 2 + 1] + bv1;
                        float mk = hf ? mk1 : mk0;
                        g_Hb[(R0 + r) * 16 + (col >> 1)] = packbf(H0 + mk, H1 + mk);
                        sAb[r * 20 + (col >> 1)] = packbf(H0, H1);
                    }
                } else {
                    int col = colg - 32;
                    float bv0 = b_G[col], bv1 = b_G[col + 1];
                    #pragma unroll
                    for (int hf = 0; hf < 2; hf++) {
                        int r = rowb + tm * 16 + g + hf * 8;
                        float mk = hf ? mk1 : mk0;
                        float g0 = 1.f / (1.f + __expf(-(c1[tm][j][hf * 2 + 0] + bv0 + mk)));
                        float g1 = 1.f / (1.f + __expf(-(c1[tm][j][hf * 2 + 1] + bv1 + mk)));
                        g_gateb[(R0 + r) * 16 + (col >> 1)] = packbf(g0, g1);
                    }
                }
            }
        }
    }
    __syncthreads();

    {
        float c2[2][2][4] = {};
        wgemm_b<2, 2, 2, 64>(c2, sAb + rowb * 20, 20, WOeu + wn * 256, g, qt);
        #pragma unroll
        for (int tm = 0; tm < 2; tm++)
            #pragma unroll
            for (int j = 0; j < 2; j++) {
                int col = wn * 16 + j * 8 + 2 * qt;
                float bo0 = b_Oe[col], bo1 = b_Oe[col + 1];
                #pragma unroll
                for (int hf = 0; hf < 2; hf++) {
                    int r = rowb + tm * 16 + g + hf * 8;
                    sX[r * 68 + col]     = c2[tm][j][hf * 2 + 0] + bo0 + sX[r * 68 + col];
                    sX[r * 68 + col + 1] = c2[tm][j][hf * 2 + 1] + bo1 + sX[r * 68 + col + 1];
                }
            }
    }
    __syncthreads();

    ln64b(sX, 68, sXb, 36, flg, flb, tid);
    __syncthreads();

    #pragma unroll
    for (int half = 0; half < 2; half++) {
        float c3[2][2][4] = {};
        int cb = wn * 32 + half * 16;
        wgemm_b<2, 2, 4, 128>(c3, sXb + rowb * 36, 36, We1u + cb * 16, g, qt);
        #pragma unroll
        for (int tm = 0; tm < 2; tm++)
            #pragma unroll
            for (int j = 0; j < 2; j++) {
                int col = cb + j * 8 + 2 * qt;
                float bb0 = b_e1[col], bb1 = b_e1[col + 1];
                #pragma unroll
                for (int hf = 0; hf < 2; hf++) {
                    int r = rowb + tm * 16 + g + hf * 8;
                    float v0 = c3[tm][j][hf * 2 + 0] + bb0;
                    float v1 = c3[tm][j][hf * 2 + 1] + bb1;
                    v0 = v0 > 0.f ? v0 : __expf(v0) - 1.f;
                    v1 = v1 > 0.f ? v1 : __expf(v1) - 1.f;
                    sTb[r * 68 + (col >> 1)] = packbf(v0, v1);
                }
            }
    }
    __syncthreads();

    {
        float c4[2][2][4] = {};
        wgemm_b<2, 2, 8, 64>(c4, sTb + rowb * 68, 68, We2u + wn * 256, g, qt);
        #pragma unroll
        for (int tm = 0; tm < 2; tm++)
            #pragma unroll
            for (int j = 0; j < 2; j++) {
                int col = wn * 16 + j * 8 + 2 * qt;
                float bz0 = b_e2[col], bz1 = b_e2[col + 1];
                #pragma unroll
                for (int hf = 0; hf < 2; hf++) {
                    int r = rowb + tm * 16 + g + hf * 8;
                    float2 ov;
                    ov.x = c4[tm][j][hf * 2 + 0] + bz0 + sX[r * 68 + col];
                    ov.y = c4[tm][j][hf * 2 + 1] + bz1 + sX[r * 68 + col + 1];
                    *(float2*)&e_out[(R0 + r) * 64 + col] = ov;
                }
            }
    }
}

// ---- eb1: softmax + gate; store normalized bf16 weights to g_Wt --------------
__global__ void __launch_bounds__(256) eb1_kernel()
{
    __shared__ float sH[256 * 36];
    __shared__ float sRed[256];
    __shared__ float sRed2[256];
    __shared__ float sInv[32];

    int tid = threadIdx.x;
    int bl  = blockIdx.x;
    int b   = bl >> 8;
    int l   = bl & 255;

    const uint4* Hg = (const uint4*)(g_Hb + (size_t)bl * 4096);
    #pragma unroll
    for (int i = 0; i < 4; i++) {
        int idx = tid + i * 256;
        int m = idx >> 2, q = idx & 3;
        uint4 hv = Hg[idx];
        uint32_t ws[4] = {hv.x, hv.y, hv.z, hv.w};
        #pragma unroll
        for (int j = 0; j < 4; j++) {
            float2 f = __bfloat1622float2(*(__nv_bfloat162*)&ws[j]);
            sH[m * 36 + q * 8 + 2 * j]     = f.x;
            sH[m * 36 + q * 8 + 2 * j + 1] = f.y;
        }
    }
    __syncthreads();

    int h = tid & 31, grp = tid >> 5;
    float pmax = -1e30f;
    for (int mm = 0; mm < 32; mm++) {
        int m = grp * 32 + mm;
        pmax = fmaxf(pmax, sH[m * 36 + h]);
    }
    sRed[grp * 32 + h] = pmax;
    __syncthreads();
    float M = -1e30f;
    #pragma unroll
    for (int gg = 0; gg < 8; gg++) M = fmaxf(M, sRed[gg * 32 + h]);

    const uint32_t* gateR = g_gateb + (size_t)bl * 4096;
    float ssum = 0.f;
    for (int mm = 0; mm < 32; mm++) {
        int m = grp * 32 + mm;
        float wv = __expf(sH[m * 36 + h] - M);
        ssum += wv;
        uint32_t gw = gateR[m * 16 + (h >> 1)];
        float2 gf = __bfloat1622float2(*(__nv_bfloat162*)&gw);
        float gate = (h & 1) ? gf.y : gf.x;
        sH[m * 36 + h] = wv * gate;
    }
    sRed2[grp * 32 + h] = ssum;
    __syncthreads();
    float S = 0.f;
    #pragma unroll
    for (int gg = 0; gg < 8; gg++) S += sRed2[gg * 32 + h];
    if (grp == 0) sInv[h] = 1.f / S;
    __syncthreads();

    int pw = tid >> 5, ln = tid & 31;
    int hh = pw * 4 + (ln >> 3), q = ln & 7;
    float invh = sInv[hh];
    size_t rowbase = (((size_t)b * 32 + hh) * 256 + l) * 128;
    #pragma unroll
    for (int i = 0; i < 4; i++) {
        int wd0 = i * 32 + q * 4;
        uint4 out;
        uint32_t* po = (uint32_t*)&out;
        #pragma unroll
        for (int ee = 0; ee < 4; ee++) {
            int m0 = 2 * (wd0 + ee);
            po[ee] = packbf(sH[m0 * 36 + hh] * invh, sH[(m0 + 1) * 36 + hh] * invh);
        }
        *(uint4*)&g_Wt[rowbase + wd0] = out;
    }
}

// ---- eb2: per-(b,h) GEMM  V_att[l, k] = W(256l x 256m) @ V_h(256m x 16k) -----
constexpr int EB2_SMEM_BYTES = (256 * 36 + 128 * 17) * 4;   // 45568

__global__ void __launch_bounds__(256) eb2_kernel()
{
    extern __shared__ uint32_t es2[];
    uint32_t* sA  = es2;            // 256 rows x 36 (32 kpair words + pad)
    uint32_t* sVb = es2 + 9216;     // 128 mpairs x 17 (16 n words + pad)

    int blk = blockIdx.x;
    int h = blk & 31, b = blk >> 5;
    int tid = threadIdx.x;
    int w = tid >> 5, g = (tid & 31) >> 2, qt = tid & 3;

    const uint32_t* vb = (const uint32_t*)g_vb + (size_t)(b * 256) * 256 + h;
    #pragma unroll
    for (int it = 0; it < 8; it++) {
        int widx = tid + it * 256;
        int mp = widx >> 4, n = widx & 15;
        int dp = n >> 1, s = n & 1;
        uint32_t w0 = vb[(size_t)(2 * mp)     * 256 + dp * 32];
        uint32_t w1 = vb[(size_t)(2 * mp + 1) * 256 + dp * 32];
        uint32_t lo = s ? (w0 >> 16) : (w0 & 0xffffu);
        uint32_t hi = s ? (w1 & 0xffff0000u) : (w1 << 16);
        sVb[mp * 17 + n] = lo | hi;
    }

    size_t Abase = ((size_t)b * 32 + h) * 256 * 128;
    float acc[2][2][4] = {};
    for (int c = 0; c < 4; c++) {
        __syncthreads();
        #pragma unroll
        for (int it = 0; it < 8; it++) {
            int v = tid + it * 256;
            int row = v >> 3, wq = v & 7;
            uint4 av = *(const uint4*)&g_Wt[Abase + (size_t)row * 128 + c * 32 + wq * 4];
            *(uint4*)&sA[row * 36 + wq * 4] = av;
        }
        __syncthreads();
        #pragma unroll
        for (int s = 0; s < 4; s++) {
            int kp0 = 8 * s + qt;
            #pragma unroll
            for (int tm = 0; tm < 2; tm++) {
                const uint32_t* Ar = sA + (w * 32 + tm * 16) * 36;
                uint32_t a0 = Ar[(g)     * 36 + kp0];
                uint32_t a1 = Ar[(g + 8) * 36 + kp0];
                uint32_t a2 = Ar[(g)     * 36 + kp0 + 4];
                uint32_t a3 = Ar[(g + 8) * 36 + kp0 + 4];
                #pragma unroll
                for (int j = 0; j < 2; j++) {
                    uint32_t b0 = sVb[(32 * c + kp0)     * 17 + j * 8 + g];
                    uint32_t b1 = sVb[(32 * c + kp0 + 4) * 17 + j * 8 + g];
                    mma16(acc[tm][j], a0, a1, a2, a3, b0, b1);
                }
            }
        }
    }
    float* Vout = g_vatt + (size_t)(b * 256) * 512 + h;
    #pragma unroll
    for (int tm = 0; tm < 2; tm++)
        #pragma unroll
        for (int j = 0; j < 2; j++) {
            int n = j * 8 + 2 * qt;
            #pragma unroll
            for (int hf = 0; hf < 2; hf++) {
                int l = w * 32 + tm * 16 + g + hf * 8;
                Vout[(size_t)l * 512 + n * 32]       = acc[tm][j][hf * 2 + 0];
                Vout[(size_t)l * 512 + (n + 1) * 32] = acc[tm][j][hf * 2 + 1];
            }
        }
}

// ---------------- launch ----------------
extern "C" void kernel_launch(void* const* d_in, const int* in_sizes, int n_in,
                              void* d_out, int out_size)
{
    const float* h         = (const float*)d_in[0];
    const float* e         = (const float*)d_in[1];
    const float* mask      = (const float*)d_in[2];
    const float* ln_h_g    = (const float*)d_in[3];
    const float* ln_h_b    = (const float*)d_in[4];
    const float* ln_e_g    = (const float*)d_in[5];
    const float* ln_e_b    = (const float*)d_in[6];
    const float* ffn_ln_h_g= (const float*)d_in[7];
    const float* ffn_ln_h_b= (const float*)d_in[8];
    const float* ffn_ln_e_g= (const float*)d_in[9];
    const float* ffn_ln_e_b= (const float*)d_in[10];
    const float* W_qkv     = (const float*)d_in[11];
    const float* b_qkv     = (const float*)d_in[12];
    const float* W_E       = (const float*)d_in[13];
    const float* b_E       = (const float*)d_in[14];
    const float* W_G       = (const float*)d_in[15];
    const float* b_G       = (const float*)d_in[16];
    const float* W_Oh      = (const float*)d_in[17];
    const float* b_Oh      = (const float*)d_in[18];
    const float* W_h1      = (const float*)d_in[19];
    const float* b_h1      = (const float*)d_in[20];
    const float* W_h2      = (const float*)d_in[21];
    const float* b_h2      = (const float*)d_in[22];
    const float* W_Oe      = (const float*)d_in[23];
    const float* b_Oe      = (const float*)d_in[24];
    const float* W_e1      = (const float*)d_in[25];
    const float* b_e1      = (const float*)d_in[26];
    const float* W_e2      = (const float*)d_in[27];
    const float* b_e2      = (const float*)d_in[28];

    float* h_out = (float*)d_out;
    float* e_out = (float*)d_out + (size_t)ROWS * DNn;

    float *p_hln, *p_qkv, *p_vatt, *p_h2, *p_hff, *p_t;
    cudaGetSymbolAddress((void**)&p_hln,  g_hln);
    cudaGetSymbolAddress((void**)&p_qkv,  g_qkv);
    cudaGetSymbolAddress((void**)&p_vatt, g_vatt);
    cudaGetSymbolAddress((void**)&p_h2,   g_h2);
    cudaGetSymbolAddress((void**)&p_hff,  g_hff);
    cudaGetSymbolAddress((void**)&p_t,    g_t);

    cudaFuncSetAttribute(ea_kernel, cudaFuncAttributeMaxDynamicSharedMemorySize,
                         EA_SMEM_BYTES);
    cudaFuncSetAttribute(qk_kernel, cudaFuncAttributeMaxDynamicSharedMemorySize,
                         QK_SMEM_BYTES);
    cudaFuncSetAttribute(eb2_kernel, cudaFuncAttributeMaxDynamicSharedMemorySize,
                         EB2_SMEM_BYTES);
    cudaFuncSetAttribute(tgemm_tf<1>, cudaFuncAttributeMaxDynamicSharedMemorySize,
                         TG_SMEM_BYTES);
    cudaFuncSetAttribute(tgemm_tf<2>, cudaFuncAttributeMaxDynamicSharedMemorySize,
                         TG_SMEM_BYTES);
    cudaFuncSetAttribute(tgemm_tf<3>, cudaFuncAttributeMaxDynamicSharedMemorySize,
                         TG_SMEM_BYTES);

    // 0) pack edge weights (bf16 fragments)
    pack_weights<<<88, 256>>>(W_E, W_G, W_Oe, W_e1, W_e2);
    // 1) h_ln
    ln512_kernel<<<ROWS, 128>>>(h, ln_h_g, ln_h_b, p_hln);
    // 2) QKV (tf32); Q -> g_qkv fp32, K/V -> g_kb/g_vb bf16 (fused pack)
    tgemm_tf<3><<<dim3(1536/64, ROWS/128), 256, TG_SMEM_BYTES>>>(p_hln, W_qkv, p_qkv,
                                                  b_qkv, nullptr, ROWS, 1536, 512);
    // 2.6) QK precompute: A_hat
    qk_kernel<<<Bn * 4 * 8, 256, QK_SMEM_BYTES>>>();
    // 3) edge pipeline (writes e_out, g_Hb(+mask), g_gateb)
    ea_kernel<<<ROWS * 4, 256, EA_SMEM_BYTES>>>(e, mask, ln_e_g, ln_e_b,
        ffn_ln_e_g, ffn_ln_e_b, b_E, b_G, b_Oe, b_e1, b_e2, e_out);
    // 4a) softmax -> normalized bf16 weights (g_Wt)
    eb1_kernel<<<ROWS, 256>>>();
    // 4b) per-head GEMM: V_att = W @ V_h  (V read once per head)
    eb2_kernel<<<Bn * 32, 256, EB2_SMEM_BYTES>>>();
    // 5) h2 = V_att @ W_Oh + b + h
    tgemm_tf<1><<<dim3(512/64, ROWS/128), 256, TG_SMEM_BYTES>>>(p_vatt, W_Oh, p_h2,
                                                 b_Oh, h, ROWS, 512, 512);
    // 6) h_ff = LN(h2)
    ln512_kernel<<<ROWS, 128>>>(p_h2, ffn_ln_h_g, ffn_ln_h_b, p_hff);
    // 7) t = elu(h_ff @ W_h1 + b)
    tgemm_tf<2><<<dim3(1024/64, ROWS/128), 256, TG_SMEM_BYTES>>>(p_hff, W_h1, p_t,
                                                  b_h1, nullptr, ROWS, 1024, 512);
    // 8) h_out = t @ W_h2 + b + h2
    tgemm_tf<1><<<dim3(512/64, ROWS/128), 256, TG_SMEM_BYTES>>>(p_t, W_h2, h_out,
                                                 b_h2, p_h2, ROWS, 512, 1024);
}

// round 17
// speedup vs baseline: 1.0988x; 1.0988x over previous
#include <cuda_runtime.h>
#include <cuda_bf16.h>
#include <math.h>
#include <stdint.h>

#define DEV_INLINE __device__ __forceinline__

constexpr int Bn = 32, Ln = 256, DNn = 512;
constexpr int ROWS = Bn * Ln;            // 8192 (b,l) rows
constexpr int EROWS = ROWS * Ln;         // 2,097,152 edge rows
constexpr int FNn = 1024;
constexpr float EPSc = 1e-5f;

// ---------------- device scratch ----------------
__device__ float g_hln[ROWS * DNn];
__device__ float g_qkv[ROWS * 3 * DNn];       // only Q region (cols 0..511) written
__device__ float g_vatt[ROWS * DNn];
__device__ float g_h2[ROWS * DNn];
__device__ float g_hff[ROWS * DNn];
__device__ float g_t[ROWS * FNn];
__device__ uint32_t g_Hb[(size_t)EROWS * 16];     // H_hat + mask, bf16x2
__device__ uint32_t g_gateb[(size_t)EROWS * 16];  // sigmoid(G+mask), bf16x2
__device__ __nv_bfloat16 g_Ab[(size_t)EROWS * 32];// A_hat (scaled), bf16
__device__ uint32_t g_Wt[(size_t)ROWS * 4096];    // softmax weights, bf16 m-pairs
// bf16 fragment-packed edge weights (see packB); bf16 K and V
__device__ __nv_bfloat16 g_WEGb[64 * 64];
__device__ __nv_bfloat16 g_WOeb[32 * 64];
__device__ __nv_bfloat16 g_We1b[64 * 128];
__device__ __nv_bfloat16 g_We2b[128 * 64];
__device__ __nv_bfloat162 g_kb[(size_t)ROWS * 256];   // [(row)*256 + dp*32 + h]
__device__ __nv_bfloat162 g_vb[(size_t)ROWS * 256];   // [(row)*256 + kp*32 + h]

DEV_INLINE uint32_t packbf(float a, float b) {
    __nv_bfloat162 h2 = __floats2bfloat162_rn(a, b);
    return *(uint32_t*)&h2;
}

DEV_INLINE float to_tf32(float x) {
    float y;
    asm("cvt.rna.tf32.f32 %0, %1;" : "=f"(y) : "f"(x));
    return y;
}

DEV_INLINE void mma8(float c[4], uint32_t a0, uint32_t a1, uint32_t a2, uint32_t a3,
                     uint32_t b0, uint32_t b1)
{
    asm volatile(
        "mma.sync.aligned.m16n8k8.row.col.f32.tf32.tf32.f32 "
        "{%0,%1,%2,%3},{%4,%5,%6,%7},{%8,%9},{%0,%1,%2,%3};"
        : "+f"(c[0]), "+f"(c[1]), "+f"(c[2]), "+f"(c[3])
        : "r"(a0), "r"(a1), "r"(a2), "r"(a3), "r"(b0), "r"(b1));
}

DEV_INLINE void mma16(float c[4], uint32_t a0, uint32_t a1, uint32_t a2, uint32_t a3,
                      uint32_t b0, uint32_t b1)
{
    asm volatile(
        "mma.sync.aligned.m16n8k16.row.col.f32.bf16.bf16.f32 "
        "{%0,%1,%2,%3},{%4,%5,%6,%7},{%8,%9},{%0,%1,%2,%3};"
        : "+f"(c[0]), "+f"(c[1]), "+f"(c[2]), "+f"(c[3])
        : "r"(a0), "r"(a1), "r"(a2), "r"(a3), "r"(b0), "r"(b1));
}

// bf16 warp GEMM, m16n8k16. A in smem as u32 (bf16x2), sb2 = u32 words per row.
template<int TM, int NTW, int S, int N>
DEV_INLINE void wgemm_b(float c[TM][NTW][4], const uint32_t* __restrict__ As, int sb2,
                        const uint32_t* __restrict__ Bp, int g, int qt)
{
    #pragma unroll
    for (int t = 0; t < (S + 1) / 2; t++) {
        uint4 bq[NTW];
        #pragma unroll
        for (int j = 0; j < NTW; j++)
            bq[j] = *(const uint4*)&Bp[(t * (N * 4) + (j * 8 + g) * 4 + qt) * 4];
        #pragma unroll
        for (int se = 0; se < 2; se++) {
            int s = 2 * t + se;
            if (s >= S) break;
            #pragma unroll
            for (int tm = 0; tm < TM; tm++) {
                const uint32_t* Ar = As + tm * 16 * sb2;
                uint32_t a0 = Ar[(g)     * sb2 + 8 * s + qt];
                uint32_t a2 = Ar[(g)     * sb2 + 8 * s + qt + 4];
                uint32_t a1 = Ar[(g + 8) * sb2 + 8 * s + qt];
                uint32_t a3 = Ar[(g + 8) * sb2 + 8 * s + qt + 4];
                #pragma unroll
                for (int j = 0; j < NTW; j++) {
                    uint32_t b0 = se ? bq[j].z : bq[j].x;
                    uint32_t b1 = se ? bq[j].w : bq[j].y;
                    mma16(c[tm][j], a0, a1, a2, a3, b0, b1);
                }
            }
        }
    }
}

// bf16 fragment pack index: element (k,n) of a KxN col-fragment weight.
DEV_INLINE int packB(int n, int k, int N) {
    int p = k >> 1, lo = k & 1;
    int qt = p & 3, half = (p >> 2) & 1, s = p >> 3;
    int t = s >> 1, se = s & 1;
    int u32i = (t * (N * 4) + n * 4 + qt) * 4 + se * 2 + half;
    return u32i * 2 + lo;
}

__global__ void pack_weights(const float* __restrict__ W_E, const float* __restrict__ W_G,
                             const float* __restrict__ W_Oe, const float* __restrict__ W_e1,
                             const float* __restrict__ W_e2)
{
    int i = blockIdx.x * 256 + threadIdx.x;
    if (i < 4096) {                       // WEG: K=64, N=64
        int k = i >> 6, n = i & 63;
        float v = n < 32 ? W_E[k * 32 + n] : W_G[k * 32 + n - 32];
        g_WEGb[packB(n, k, 64)] = __float2bfloat16(v);
    } else if (i < 6144) {                // WOe: K=32, N=64
        int j = i - 4096; int k = j >> 6, n = j & 63;
        g_WOeb[packB(n, k, 64)] = __float2bfloat16(W_Oe[j]);
    } else if (i < 14336) {               // We1: K=64, N=128
        int j = i - 6144; int k = j >> 7, n = j & 127;
        g_We1b[packB(n, k, 128)] = __float2bfloat16(W_e1[j]);
    } else if (i < 22528) {               // We2: K=128, N=64
        int j = i - 14336; int k = j >> 6, n = j & 63;
        g_We2b[packB(n, k, 64)] = __float2bfloat16(W_e2[j]);
    }
}

// ---------------- QK precompute: A_hat, 4 l's per thread --------------------
constexpr int QK_SMEM_BYTES = 64 * 256 * 4;   // 65536

__global__ void __launch_bounds__(256, 2) qk_kernel()
{
    extern __shared__ uint32_t ks[];   // [64][256] bf16x2 words
    int blk = blockIdx.x;
    int lt = blk & 7, mt = (blk >> 3) & 3, b = blk >> 5;
    int m0 = mt * 64, l0 = lt * 32;
    int tid = threadIdx.x;

    const uint4* Ksrc = (const uint4*)(g_kb + ((size_t)(b * 256) + m0) * 256);
    uint4* Kdst = (uint4*)ks;
    #pragma unroll
    for (int i = 0; i < 16; i++)
        Kdst[tid + i * 256] = Ksrc[tid + i * 256];
    __syncthreads();

    int h = tid & 31, lg = tid >> 5;
    int l = l0 + lg * 4;
    int bl = b * 256 + l;

    float q[4][16];
    #pragma unroll
    for (int li = 0; li < 4; li++) {
        const float* Qp = g_qkv + (size_t)(bl + li) * 1536 + h;
        #pragma unroll
        for (int d = 0; d < 16; d++) q[li][d] = Qp[d * 32];
    }

    __nv_bfloat16* Ad0 = g_Ab + ((size_t)(bl + 0) * 256 + m0) * 32 + h;
    __nv_bfloat16* Ad1 = g_Ab + ((size_t)(bl + 1) * 256 + m0) * 32 + h;
    __nv_bfloat16* Ad2 = g_Ab + ((size_t)(bl + 2) * 256 + m0) * 32 + h;
    __nv_bfloat16* Ad3 = g_Ab + ((size_t)(bl + 3) * 256 + m0) * 32 + h;

    #pragma unroll 2
    for (int m = 0; m < 64; m++) {
        const uint32_t* Kp = ks + m * 256 + h;
        float kf[16];
        #pragma unroll
        for (int dp = 0; dp < 8; dp++) {
            uint32_t wv = Kp[dp * 32];
            kf[2 * dp]     = __uint_as_float(wv << 16);
            kf[2 * dp + 1] = __uint_as_float(wv & 0xffff0000u);
        }
        float a0 = 0.f, a1 = 0.f, a2 = 0.f, a3 = 0.f;
        #pragma unroll
        for (int d = 0; d < 16; d++) {
            a0 += q[0][d] * kf[d];
            a1 += q[1][d] * kf[d];
            a2 += q[2][d] * kf[d];
            a3 += q[3][d] * kf[d];
        }
        Ad0[(size_t)m * 32] = __float2bfloat16(a0 * 0.25f);
        Ad1[(size_t)m * 32] = __float2bfloat16(a1 * 0.25f);
        Ad2[(size_t)m * 32] = __float2bfloat16(a2 * 0.25f);
        Ad3[(size_t)m * 32] = __float2bfloat16(a3 * 0.25f);
    }
}

// ---------------- LayerNorm over 512, one block per row ----------------
__global__ void __launch_bounds__(128) ln512_kernel(
    const float* __restrict__ x, const float* __restrict__ g,
    const float* __restrict__ b, float* __restrict__ y)
{
    int row = blockIdx.x, tid = threadIdx.x;
    const float4* xr = (const float4*)(x + (size_t)row * 512);
    float4 v = xr[tid];
    float s  = v.x + v.y + v.z + v.w;
    float s2 = v.x*v.x + v.y*v.y + v.z*v.z + v.w*v.w;
    #pragma unroll
    for (int o = 16; o; o >>= 1) {
        s  += __shfl_xor_sync(0xffffffffu, s,  o);
        s2 += __shfl_xor_sync(0xffffffffu, s2, o);
    }
    __shared__ float aS[4], aS2[4];
    if ((tid & 31) == 0) { aS[tid >> 5] = s; aS2[tid >> 5] = s2; }
    __syncthreads();
    s  = aS[0] + aS[1] + aS[2] + aS[3];
    s2 = aS2[0] + aS2[1] + aS2[2] + aS2[3];
    float mean = s * (1.f / 512.f);
    float rstd = rsqrtf(s2 * (1.f / 512.f) - mean * mean + EPSc);
    int c = tid * 4;
    float4 gv = *(const float4*)(g + c);
    float4 bv = *(const float4*)(b + c);
    float4 o;
    o.x = (v.x - mean) * rstd * gv.x + bv.x;
    o.y = (v.y - mean) * rstd * gv.y + bv.y;
    o.z = (v.z - mean) * rstd * gv.z + bv.z;
    o.w = (v.w - mean) * rstd * gv.w + bv.w;
    ((float4*)(y + (size_t)row * 512))[tid] = o;
}

// ------- tf32 tensor GEMM, 64-bit paired smem operands, conflict-free strides --
// A pairs: As2[r][ks*4+qt] = (A[r][ks*8+qt], A[r][ks*8+qt+4])     stride 36 (≡4 mod 16)
// B pairs: Bs2[ks*4+qt][n] = (B[ks*8+qt][n], B[ks*8+qt+4][n])     stride 68 (≡4 mod 16)
constexpr int TG_SMEM_BYTES = (128 * 36 + 32 * 68) * 8;   // 54272
template<int MODE>
__global__ void __launch_bounds__(256) tgemm_tf(
    const float* __restrict__ A, const float* __restrict__ B, float* __restrict__ C,
    const float* __restrict__ bias, const float* __restrict__ res,
    int M, int N, int K)
{
    extern __shared__ float ts[];
    float2* As2 = (float2*)ts;                  // 128 x 36 float2
    float2* Bs2 = (float2*)(ts + 128 * 36 * 2); // 32 x 68 float2
    int tid = threadIdx.x;
    int row0 = blockIdx.y * 128, col0 = blockIdx.x * 64;
    int w = tid >> 5;
    int g = (tid & 31) >> 2, qt = tid & 3;
    float acc[8][4] = {};

    for (int k0 = 0; k0 < K; k0 += 64) {
        // stage A: 128 rows x 8 octets, pairs (c, c+4)
        #pragma unroll
        for (int it = 0; it < 4; it++) {
            int idx = tid + it * 256;
            int r = idx >> 3, oct = idx & 7;
            const float* ap = &A[(size_t)(row0 + r) * K + k0 + oct * 8];
            float4 v0 = *(const float4*)ap;
            float4 v1 = *(const float4*)(ap + 4);
            float2* dst = As2 + r * 36 + oct * 4;
            dst[0] = make_float2(to_tf32(v0.x), to_tf32(v1.x));
            dst[1] = make_float2(to_tf32(v0.y), to_tf32(v1.y));
            dst[2] = make_float2(to_tf32(v0.z), to_tf32(v1.z));
            dst[3] = make_float2(to_tf32(v0.w), to_tf32(v1.w));
        }
        // stage B: 32 pair-rows x 16 col-quads, pairs (k+qt, k+qt+4)
        #pragma unroll
        for (int it = 0; it < 2; it++) {
            int idx = tid + it * 256;
            int p = idx >> 4, quad = idx & 15;
            int ksr = p >> 2, qtr = p & 3;
            const float* bp = &B[(size_t)(k0 + ksr * 8 + qtr) * N + col0 + quad * 4];
            float4 v0 = *(const float4*)bp;
            float4 v1 = *(const float4*)(bp + 4 * N);
            float2* dst = Bs2 + p * 68 + quad * 4;
            dst[0] = make_float2(to_tf32(v0.x), to_tf32(v1.x));
            dst[1] = make_float2(to_tf32(v0.y), to_tf32(v1.y));
            dst[2] = make_float2(to_tf32(v0.z), to_tf32(v1.z));
            dst[3] = make_float2(to_tf32(v0.w), to_tf32(v1.w));
        }
        __syncthreads();
        const float2* Ar = As2 + (w * 16) * 36;
        #pragma unroll
        for (int ks = 0; ks < 8; ks++) {
            float2 Aw0 = Ar[(g)     * 36 + ks * 4 + qt];
            float2 Aw1 = Ar[(g + 8) * 36 + ks * 4 + qt];
            uint32_t a0 = __float_as_uint(Aw0.x), a2 = __float_as_uint(Aw0.y);
            uint32_t a1 = __float_as_uint(Aw1.x), a3 = __float_as_uint(Aw1.y);
            const float2* Br = Bs2 + (ks * 4 + qt) * 68 + g;
            #pragma unroll
            for (int j = 0; j < 8; j++) {
                float2 Bw = Br[j * 8];
                mma8(acc[j], a0, a1, a2, a3,
                     __float_as_uint(Bw.x), __float_as_uint(Bw.y));
            }
        }
        __syncthreads();
    }
    if (MODE == 3 && col0 >= 512) {
        bool isK = (col0 < 1024);
        uint32_t* dstBase = (uint32_t*)(isK ? g_kb : g_vb);
        int obase = col0 - (isK ? 512 : 1024);
        #pragma unroll
        for (int j = 0; j < 4; j++) {
            int c = col0 + j * 8 + 2 * qt;
            int o = obase + j * 8 + 2 * qt;
            int dp = o >> 6, hh = o & 31;
            float b00 = bias[c],      b01 = bias[c + 1];
            float b10 = bias[c + 32], b11 = bias[c + 33];
            #pragma unroll
            for (int hf = 0; hf < 2; hf++) {
                int r = row0 + w * 16 + g + hf * 8;
                uint32_t* d = dstBase + (size_t)r * 256 + dp * 32 + hh;
                d[0] = packbf(acc[j][hf * 2 + 0] + b00, acc[j + 4][hf * 2 + 0] + b10);
                d[1] = packbf(acc[j][hf * 2 + 1] + b01, acc[j + 4][hf * 2 + 1] + b11);
            }
        }
        return;
    }
    #pragma unroll
    for (int j = 0; j < 8; j++) {
        int col = col0 + j * 8 + 2 * qt;
        #pragma unroll
        for (int hf = 0; hf < 2; hf++) {
            int r = row0 + w * 16 + g + hf * 8;
            float v0 = acc[j][hf * 2 + 0] + bias[col];
            float v1 = acc[j][hf * 2 + 1] + bias[col + 1];
            if (MODE == 1) {
                float2 rv = *(const float2*)&res[(size_t)r * N + col];
                v0 += rv.x; v1 += rv.y;
            }
            if (MODE == 2) {
                v0 = v0 > 0.f ? v0 : __expf(v0) - 1.f;
                v1 = v1 > 0.f ? v1 : __expf(v1) - 1.f;
            }
            float2 ov; ov.x = v0; ov.y = v1;
            *(float2*)&C[(size_t)r * N + col] = ov;
        }
    }
}

// LN of 64 rows x 64 cols: fp32 src (stride sstr) -> bf16x2 dst (dsb2 u32/row).
DEV_INLINE void ln64b(const float* __restrict__ src, int sstr, uint32_t* __restrict__ dst,
                      int dsb2, const float* __restrict__ gam,
                      const float* __restrict__ bet, int tid)
{
    int r = tid >> 2, sub = tid & 3;
    const float* p = src + r * sstr + sub * 16;
    float x[16]; float s = 0.f, s2 = 0.f;
    #pragma unroll
    for (int i = 0; i < 16; i += 4) {
        float4 v = *(const float4*)(p + i);
        x[i] = v.x; x[i+1] = v.y; x[i+2] = v.z; x[i+3] = v.w;
    }
    #pragma unroll
    for (int i = 0; i < 16; i++) { s += x[i]; s2 += x[i] * x[i]; }
    s  += __shfl_xor_sync(0xffffffffu, s, 1);  s  += __shfl_xor_sync(0xffffffffu, s, 2);
    s2 += __shfl_xor_sync(0xffffffffu, s2, 1); s2 += __shfl_xor_sync(0xffffffffu, s2, 2);
    float mean = s * (1.f / 64.f);
    float rstd = rsqrtf(s2 * (1.f / 64.f) - mean * mean + EPSc);
    uint32_t* d = dst + r * dsb2 + sub * 8;
    #pragma unroll
    for (int i = 0; i < 16; i += 2) {
        int c = sub * 16 + i;
        float y0 = (x[i]     - mean) * rstd * gam[c]     + bet[c];
        float y1 = (x[i + 1] - mean) * rstd * gam[c + 1] + bet[c + 1];
        d[i >> 1] = packbf(y0, y1);
    }
}

// Fused: load e tile from global, keep fp32 copy in sX, LN -> bf16x2 sXb.
DEV_INLINE void ln64g(const float* __restrict__ eg, float* __restrict__ sX,
                      uint32_t* __restrict__ sXb,
                      const float* __restrict__ gam, const float* __restrict__ bet, int tid)
{
    int r = tid >> 2, sub = tid & 3;
    const float* p = eg + r * 64 + sub * 16;
    float* q = sX + r * 68 + sub * 16;
    float x[16]; float s = 0.f, s2 = 0.f;
    #pragma unroll
    for (int i = 0; i < 16; i += 4) {
        float4 v = *(const float4*)(p + i);
        *(float4*)(q + i) = v;
        x[i] = v.x; x[i+1] = v.y; x[i+2] = v.z; x[i+3] = v.w;
    }
    #pragma unroll
    for (int i = 0; i < 16; i++) { s += x[i]; s2 += x[i] * x[i]; }
    s  += __shfl_xor_sync(0xffffffffu, s, 1);  s  += __shfl_xor_sync(0xffffffffu, s, 2);
    s2 += __shfl_xor_sync(0xffffffffu, s2, 1); s2 += __shfl_xor_sync(0xffffffffu, s2, 2);
    float mean = s * (1.f / 64.f);
    float rstd = rsqrtf(s2 * (1.f / 64.f) - mean * mean + EPSc);
    uint32_t* d = sXb + r * 36 + sub * 8;
    #pragma unroll
    for (int i = 0; i < 16; i += 2) {
        int c = sub * 16 + i;
        float y0 = (x[i]     - mean) * rstd * gam[c]     + bet[c];
        float y1 = (x[i + 1] - mean) * rstd * gam[c + 1] + bet[c + 1];
        d[i >> 1] = packbf(y0, y1);
    }
}

// ---------------- edge pipeline: 64 rows/CTA, 256 threads, 4 CTA/SM ------------
constexpr int EA_SMEM_BYTES = (4352 + 2304 + 1280 + 4352) * 4;  // 49152

__global__ void __launch_bounds__(256, 4) ea_kernel(
    const float* __restrict__ e, const float* __restrict__ mask,
    const float* __restrict__ lng, const float* __restrict__ lnb,
    const float* __restrict__ flg, const float* __restrict__ flb,
    const float* __restrict__ b_E,  const float* __restrict__ b_G,
    const float* __restrict__ b_Oe, const float* __restrict__ b_e1,
    const float* __restrict__ b_e2,
    float* __restrict__ e_out)
{
    extern __shared__ float sm[];
    float*    sX  = sm;                          // 64 x 68 fp32 (e, then e2)
    uint32_t* sXb = (uint32_t*)(sm + 4352);      // 64 x 36 u32 (eln/eff bf16x2)
    uint32_t* sAb = (uint32_t*)(sm + 6656);      // 64 x 20 u32 (H bf16x2)
    uint32_t* sTb = (uint32_t*)(sm + 7936);      // 64 x 68 u32 (T bf16x2)

    int tid = threadIdx.x;
    int blk = blockIdx.x;
    int bl  = blk >> 2, quad = blk & 3;
    int m0  = quad * 64;
    size_t R0 = (size_t)bl * 256 + m0;

    int w   = tid >> 5;
    int wm2 = w >> 2, wn = w & 3;
    int g   = (tid & 31) >> 2, qt = tid & 3;
    int rowb = wm2 * 32;

    const uint32_t* WEGu = (const uint32_t*)g_WEGb;
    const uint32_t* WOeu = (const uint32_t*)g_WOeb;
    const uint32_t* We1u = (const uint32_t*)g_We1b;
    const uint32_t* We2u = (const uint32_t*)g_We2b;

    ln64g(e + R0 * 64, sX, sXb, lng, lnb, tid);
    __syncthreads();

    float c1[2][2][4] = {};
    wgemm_b<2, 2, 4, 64>(c1, sXb + rowb * 36, 36, WEGu + wn * 256, g, qt);
    __syncthreads();

    {
        #pragma unroll
        for (int tm = 0; tm < 2; tm++) {
            float mk0 = mask[(size_t)bl * 256 + m0 + rowb + tm * 16 + g];
            float mk1 = mask[(size_t)bl * 256 + m0 + rowb + tm * 16 + g + 8];
            #pragma unroll
            for (int j = 0; j < 2; j++) {
                int colg = wn * 16 + j * 8 + 2 * qt;
                if (wn < 2) {
                    int col = colg;
                    float bv0 = b_E[col], bv1 = b_E[col + 1];
                    #pragma unroll
                    for (int hf = 0; hf < 2; hf++) {
                        int r = rowb + tm * 16 + g + hf * 8;
                        uint32_t aw = ((const uint32_t*)g_Ab)[(R0 + r) * 16 + (col >> 1)];
                        float2 Af = __bfloat1622float2(*(__nv_bfloat162*)&aw);
                        float H0 = fminf(fmaxf(Af.x, -5.f), 5.f) + c1[tm][j][hf * 2 + 0] + bv0;
                        float H1 = fminf(fmaxf(Af.y, -5.f), 5.f) + c1[tm][j][hf * 2 + 1] + bv1;
                        float mk = hf ? mk1 : mk0;
                        g_Hb[(R0 + r) * 16 + (col >> 1)] = packbf(H0 + mk, H1 + mk);
                        sAb[r * 20 + (col >> 1)] = packbf(H0, H1);
                    }
                } else {
                    int col = colg - 32;
                    float bv0 = b_G[col], bv1 = b_G[col + 1];
                    #pragma unroll
                    for (int hf = 0; hf < 2; hf++) {
                        int r = rowb + tm * 16 + g + hf * 8;
                        float mk = hf ? mk1 : mk0;
                        float g0 = 1.f / (1.f + __expf(-(c1[tm][j][hf * 2 + 0] + bv0 + mk)));
                        float g1 = 1.f / (1.f + __expf(-(c1[tm][j][hf * 2 + 1] + bv1 + mk)));
                        g_gateb[(R0 + r) * 16 + (col >> 1)] = packbf(g0, g1);
                    }
                }
            }
        }
    }
    __syncthreads();

    {
        float c2[2][2][4] = {};
        wgemm_b<2, 2, 2, 64>(c2, sAb + rowb * 20, 20, WOeu + wn * 256, g, qt);
        #pragma unroll
        for (int tm = 0; tm < 2; tm++)
            #pragma unroll
            for (int j = 0; j < 2; j++) {
                int col = wn * 16 + j * 8 + 2 * qt;
                float bo0 = b_Oe[col], bo1 = b_Oe[col + 1];
                #pragma unroll
                for (int hf = 0; hf < 2; hf++) {
                    int r = rowb + tm * 16 + g + hf * 8;
                    sX[r * 68 + col]     = c2[tm][j][hf * 2 + 0] + bo0 + sX[r * 68 + col];
                    sX[r * 68 + col + 1] = c2[tm][j][hf * 2 + 1] + bo1 + sX[r * 68 + col + 1];
                }
            }
    }
    __syncthreads();

    ln64b(sX, 68, sXb, 36, flg, flb, tid);
    __syncthreads();

    #pragma unroll
    for (int half = 0; half < 2; half++) {
        float c3[2][2][4] = {};
        int cb = wn * 32 + half * 16;
        wgemm_b<2, 2, 4, 128>(c3, sXb + rowb * 36, 36, We1u + cb * 16, g, qt);
        #pragma unroll
        for (int tm = 0; tm < 2; tm++)
            #pragma unroll
            for (int j = 0; j < 2; j++) {
                int col = cb + j * 8 + 2 * qt;
                float bb0 = b_e1[col], bb1 = b_e1[col + 1];
                #pragma unroll
                for (int hf = 0; hf < 2; hf++) {
                    int r = rowb + tm * 16 + g + hf * 8;
                    float v0 = c3[tm][j][hf * 2 + 0] + bb0;
                    float v1 = c3[tm][j][hf * 2 + 1] + bb1;
                    v0 = v0 > 0.f ? v0 : __expf(v0) - 1.f;
                    v1 = v1 > 0.f ? v1 : __expf(v1) - 1.f;
                    sTb[r * 68 + (col >> 1)] = packbf(v0, v1);
                }
            }
    }
    __syncthreads();

    {
        float c4[2][2][4] = {};
        wgemm_b<2, 2, 8, 64>(c4, sTb + rowb * 68, 68, We2u + wn * 256, g, qt);
        #pragma unroll
        for (int tm = 0; tm < 2; tm++)
            #pragma unroll
            for (int j = 0; j < 2; j++) {
                int col = wn * 16 + j * 8 + 2 * qt;
                float bz0 = b_e2[col], bz1 = b_e2[col + 1];
                #pragma unroll
                for (int hf = 0; hf < 2; hf++) {
                    int r = rowb + tm * 16 + g + hf * 8;
                    float2 ov;
                    ov.x = c4[tm][j][hf * 2 + 0] + bz0 + sX[r * 68 + col];
                    ov.y = c4[tm][j][hf * 2 + 1] + bz1 + sX[r * 68 + col + 1];
                    *(float2*)&e_out[(R0 + r) * 64 + col] = ov;
                }
            }
    }
}

// ---- eb1: softmax + gate; store normalized bf16 weights to g_Wt --------------
__global__ void __launch_bounds__(256) eb1_kernel()
{
    __shared__ float sH[256 * 36];
    __shared__ float sRed[256];
    __shared__ float sRed2[256];
    __shared__ float sInv[32];

    int tid = threadIdx.x;
    int bl  = blockIdx.x;
    int b   = bl >> 8;
    int l   = bl & 255;

    const uint4* Hg = (const uint4*)(g_Hb + (size_t)bl * 4096);
    #pragma unroll
    for (int i = 0; i < 4; i++) {
        int idx = tid + i * 256;
        int m = idx >> 2, q = idx & 3;
        uint4 hv = Hg[idx];
        uint32_t ws[4] = {hv.x, hv.y, hv.z, hv.w};
        #pragma unroll
        for (int j = 0; j < 4; j++) {
            float2 f = __bfloat1622float2(*(__nv_bfloat162*)&ws[j]);
            sH[m * 36 + q * 8 + 2 * j]     = f.x;
            sH[m * 36 + q * 8 + 2 * j + 1] = f.y;
        }
    }
    __syncthreads();

    int h = tid & 31, grp = tid >> 5;
    float pmax = -1e30f;
    for (int mm = 0; mm < 32; mm++) {
        int m = grp * 32 + mm;
        pmax = fmaxf(pmax, sH[m * 36 + h]);
    }
    sRed[grp * 32 + h] = pmax;
    __syncthreads();
    float M = -1e30f;
    #pragma unroll
    for (int gg = 0; gg < 8; gg++) M = fmaxf(M, sRed[gg * 32 + h]);

    const uint32_t* gateR = g_gateb + (size_t)bl * 4096;
    float ssum = 0.f;
    for (int mm = 0; mm < 32; mm++) {
        int m = grp * 32 + mm;
        float wv = __expf(sH[m * 36 + h] - M);
        ssum += wv;
        uint32_t gw = gateR[m * 16 + (h >> 1)];
        float2 gf = __bfloat1622float2(*(__nv_bfloat162*)&gw);
        float gate = (h & 1) ? gf.y : gf.x;
        sH[m * 36 + h] = wv * gate;
    }
    sRed2[grp * 32 + h] = ssum;
    __syncthreads();
    float S = 0.f;
    #pragma unroll
    for (int gg = 0; gg < 8; gg++) S += sRed2[gg * 32 + h];
    if (grp == 0) sInv[h] = 1.f / S;
    __syncthreads();

    int pw = tid >> 5, ln = tid & 31;
    int hh = pw * 4 + (ln >> 3), q = ln & 7;
    float invh = sInv[hh];
    size_t rowbase = (((size_t)b * 32 + hh) * 256 + l) * 128;
    #pragma unroll
    for (int i = 0; i < 4; i++) {
        int wd0 = i * 32 + q * 4;
        uint4 out;
        uint32_t* po = (uint32_t*)&out;
        #pragma unroll
        for (int ee = 0; ee < 4; ee++) {
            int m0 = 2 * (wd0 + ee);
            po[ee] = packbf(sH[m0 * 36 + hh] * invh, sH[(m0 + 1) * 36 + hh] * invh);
        }
        *(uint4*)&g_Wt[rowbase + wd0] = out;
    }
}

// ---- eb2: per-(b,h) GEMM  V_att[l, k] = W(256l x 256m) @ V_h(256m x 16k) -----
constexpr int EB2_SMEM_BYTES = (256 * 36 + 128 * 17) * 4;   // 45568

__global__ void __launch_bounds__(256) eb2_kernel()
{
    extern __shared__ uint32_t es2[];
    uint32_t* sA  = es2;            // 256 rows x 36 (32 kpair words + pad)
    uint32_t* sVb = es2 + 9216;     // 128 mpairs x 17 (16 n words + pad)

    int blk = blockIdx.x;
    int h = blk & 31, b = blk >> 5;
    int tid = threadIdx.x;
    int w = tid >> 5, g = (tid & 31) >> 2, qt = tid & 3;

    const uint32_t* vb = (const uint32_t*)g_vb + (size_t)(b * 256) * 256 + h;
    #pragma unroll
    for (int it = 0; it < 8; it++) {
        int widx = tid + it * 256;
        int mp = widx >> 4, n = widx & 15;
        int dp = n >> 1, s = n & 1;
        uint32_t w0 = vb[(size_t)(2 * mp)     * 256 + dp * 32];
        uint32_t w1 = vb[(size_t)(2 * mp + 1) * 256 + dp * 32];
        uint32_t lo = s ? (w0 >> 16) : (w0 & 0xffffu);
        uint32_t hi = s ? (w1 & 0xffff0000u) : (w1 << 16);
        sVb[mp * 17 + n] = lo | hi;
    }

    size_t Abase = ((size_t)b * 32 + h) * 256 * 128;
    float acc[2][2][4] = {};
    for (int c = 0; c < 4; c++) {
        __syncthreads();
        #pragma unroll
        for (int it = 0; it < 8; it++) {
            int v = tid + it * 256;
            int row = v >> 3, wq = v & 7;
            uint4 av = *(const uint4*)&g_Wt[Abase + (size_t)row * 128 + c * 32 + wq * 4];
            *(uint4*)&sA[row * 36 + wq * 4] = av;
        }
        __syncthreads();
        #pragma unroll
        for (int s = 0; s < 4; s++) {
            int kp0 = 8 * s + qt;
            #pragma unroll
            for (int tm = 0; tm < 2; tm++) {
                const uint32_t* Ar = sA + (w * 32 + tm * 16) * 36;
                uint32_t a0 = Ar[(g)     * 36 + kp0];
                uint32_t a1 = Ar[(g + 8) * 36 + kp0];
                uint32_t a2 = Ar[(g)     * 36 + kp0 + 4];
                uint32_t a3 = Ar[(g + 8) * 36 + kp0 + 4];
                #pragma unroll
                for (int j = 0; j < 2; j++) {
                    uint32_t b0 = sVb[(32 * c + kp0)     * 17 + j * 8 + g];
                    uint32_t b1 = sVb[(32 * c + kp0 + 4) * 17 + j * 8 + g];
                    mma16(acc[tm][j], a0, a1, a2, a3, b0, b1);
                }
            }
        }
    }
    float* Vout = g_vatt + (size_t)(b * 256) * 512 + h;
    #pragma unroll
    for (int tm = 0; tm < 2; tm++)
        #pragma unroll
        for (int j = 0; j < 2; j++) {
            int n = j * 8 + 2 * qt;
            #pragma unroll
            for (int hf = 0; hf < 2; hf++) {
                int l = w * 32 + tm * 16 + g + hf * 8;
                Vout[(size_t)l * 512 + n * 32]       = acc[tm][j][hf * 2 + 0];
                Vout[(size_t)l * 512 + (n + 1) * 32] = acc[tm][j][hf * 2 + 1];
            }
        }
}

// ---------------- launch ----------------
extern "C" void kernel_launch(void* const* d_in, const int* in_sizes, int n_in,
                              void* d_out, int out_size)
{
    const float* h         = (const float*)d_in[0];
    const float* e         = (const float*)d_in[1];
    const float* mask      = (const float*)d_in[2];
    const float* ln_h_g    = (const float*)d_in[3];
    const float* ln_h_b    = (const float*)d_in[4];
    const float* ln_e_g    = (const float*)d_in[5];
    const float* ln_e_b    = (const float*)d_in[6];
    const float* ffn_ln_h_g= (const float*)d_in[7];
    const float* ffn_ln_h_b= (const float*)d_in[8];
    const float* ffn_ln_e_g= (const float*)d_in[9];
    const float* ffn_ln_e_b= (const float*)d_in[10];
    const float* W_qkv     = (const float*)d_in[11];
    const float* b_qkv     = (const float*)d_in[12];
    const float* W_E       = (const float*)d_in[13];
    const float* b_E       = (const float*)d_in[14];
    const float* W_G       = (const float*)d_in[15];
    const float* b_G       = (const float*)d_in[16];
    const float* W_Oh      = (const float*)d_in[17];
    const float* b_Oh      = (const float*)d_in[18];
    const float* W_h1      = (const float*)d_in[19];
    const float* b_h1      = (const float*)d_in[20];
    const float* W_h2      = (const float*)d_in[21];
    const float* b_h2      = (const float*)d_in[22];
    const float* W_Oe      = (const float*)d_in[23];
    const float* b_Oe      = (const float*)d_in[24];
    const float* W_e1      = (const float*)d_in[25];
    const float* b_e1      = (const float*)d_in[26];
    const float* W_e2      = (const float*)d_in[27];
    const float* b_e2      = (const float*)d_in[28];

    float* h_out = (float*)d_out;
    float* e_out = (float*)d_out + (size_t)ROWS * DNn;

    float *p_hln, *p_qkv, *p_vatt, *p_h2, *p_hff, *p_t;
    cudaGetSymbolAddress((void**)&p_hln,  g_hln);
    cudaGetSymbolAddress((void**)&p_qkv,  g_qkv);
    cudaGetSymbolAddress((void**)&p_vatt, g_vatt);
    cudaGetSymbolAddress((void**)&p_h2,   g_h2);
    cudaGetSymbolAddress((void**)&p_hff,  g_hff);
    cudaGetSymbolAddress((void**)&p_t,    g_t);

    cudaFuncSetAttribute(ea_kernel, cudaFuncAttributeMaxDynamicSharedMemorySize,
                         EA_SMEM_BYTES);
    cudaFuncSetAttribute(qk_kernel, cudaFuncAttributeMaxDynamicSharedMemorySize,
                         QK_SMEM_BYTES);
    cudaFuncSetAttribute(eb2_kernel, cudaFuncAttributeMaxDynamicSharedMemorySize,
                         EB2_SMEM_BYTES);
    cudaFuncSetAttribute(tgemm_tf<1>, cudaFuncAttributeMaxDynamicSharedMemorySize,
                         TG_SMEM_BYTES);
    cudaFuncSetAttribute(tgemm_tf<2>, cudaFuncAttributeMaxDynamicSharedMemorySize,
                         TG_SMEM_BYTES);
    cudaFuncSetAttribute(tgemm_tf<3>, cudaFuncAttributeMaxDynamicSharedMemorySize,
                         TG_SMEM_BYTES);

    // 0) pack edge weights (bf16 fragments)
    pack_weights<<<88, 256>>>(W_E, W_G, W_Oe, W_e1, W_e2);
    // 1) h_ln
    ln512_kernel<<<ROWS, 128>>>(h, ln_h_g, ln_h_b, p_hln);
    // 2) QKV (tf32); Q -> g_qkv fp32, K/V -> g_kb/g_vb bf16 (fused pack)
    tgemm_tf<3><<<dim3(1536/64, ROWS/128), 256, TG_SMEM_BYTES>>>(p_hln, W_qkv, p_qkv,
                                                  b_qkv, nullptr, ROWS, 1536, 512);
    // 2.6) QK precompute: A_hat
    qk_kernel<<<Bn * 4 * 8, 256, QK_SMEM_BYTES>>>();
    // 3) edge pipeline (writes e_out, g_Hb(+mask), g_gateb)
    ea_kernel<<<ROWS * 4, 256, EA_SMEM_BYTES>>>(e, mask, ln_e_g, ln_e_b,
        ffn_ln_e_g, ffn_ln_e_b, b_E, b_G, b_Oe, b_e1, b_e2, e_out);
    // 4a) softmax -> normalized bf16 weights (g_Wt)
    eb1_kernel<<<ROWS, 256>>>();
    // 4b) per-head GEMM: V_att = W @ V_h  (V read once per head)
    eb2_kernel<<<Bn * 32, 256, EB2_SMEM_BYTES>>>();
    // 5) h2 = V_att @ W_Oh + b + h
    tgemm_tf<1><<<dim3(512/64, ROWS/128), 256, TG_SMEM_BYTES>>>(p_vatt, W_Oh, p_h2,
                                                 b_Oh, h, ROWS, 512, 512);
    // 6) h_ff = LN(h2)
    ln512_kernel<<<ROWS, 128>>>(p_h2, ffn_ln_h_g, ffn_ln_h_b, p_hff);
    // 7) t = elu(h_ff @ W_h1 + b)
    tgemm_tf<2><<<dim3(1024/64, ROWS/128), 256, TG_SMEM_BYTES>>>(p_hff, W_h1, p_t,
                                                  b_h1, nullptr, ROWS, 1024, 512);
    // 8) h_out = t @ W_h2 + b + h2
    tgemm_tf<1><<<dim3(512/64, ROWS/128), 256, TG_SMEM_BYTES>>>(p_t, W_h2, h_out,
                                                 b_h2, p_h2, ROWS, 512, 1024);
}